// round 12
// baseline (speedup 1.0000x reference)
#include <cuda_runtime.h>
#include <cstdint>

typedef unsigned long long ull;

#define N_OBJ   4096
#define OBJ_DIM 1024
#define N_PAIRS 65536

// Scratch (device globals: no allocation allowed). 16B-aligned for float4 access.
// g_M layout: [c16][k], c16 in 0..15. c16<8: M[c][k] (sub half, k<1024 of W1 cols),
//             c16>=8: M[c-8][1024+k] (obj half).
__device__ __align__(16) float g_M[16 * 1024];   // 64 KB, ZERO before kernel A (atomics).
__device__ __align__(16) float g_cvec[8];        // W2@b1 + b2
__device__ __align__(16) float g_P[N_OBJ * 16];  // per-object projections (obj half + cvec)
__device__ int g_fmt;                            // 1 = pairs stored as int32, 0 = int64

// ---------------------------------------------------------------------------
// packed f32x2 helpers (Blackwell FFMA2 path)
// ---------------------------------------------------------------------------
__device__ __forceinline__ ull ffma2(ull a, ull b, ull c) {
    ull d;
    asm("fma.rn.f32x2 %0, %1, %2, %3;" : "=l"(d) : "l"(a), "l"(b), "l"(c));
    return d;
}
__device__ __forceinline__ ull pk2(float lo, float hi) {
    ull r;
    asm("mov.b64 %0, {%1, %2};" : "=l"(r) : "f"(lo), "f"(hi));
    return r;
}

// ---------------------------------------------------------------------------
// kDetect: decide pairs dtype. Read only the first 131072 int32 words (valid
// under BOTH hypotheses: int32 buffer = 131072 ints; int64 buffer = 262144).
// Under int64, odd words are high halves of indices < 4096 -> all zero.
// Under int32, odd words are 65536 random obj indices -> OR is nonzero.
// Deterministic: pure function of the input buffer.
// ---------------------------------------------------------------------------
__global__ __launch_bounds__(256) void kDetect(const int* __restrict__ pairs_i32) {
    __shared__ int s_or;
    if (threadIdx.x == 0) s_or = 0;
    __syncthreads();
    int v = 0;
    for (int i = threadIdx.x * 2 + 1; i < 131072; i += 512)
        v |= pairs_i32[i];
    #pragma unroll
    for (int o = 16; o; o >>= 1) v |= __shfl_xor_sync(0xffffffffu, v, o);
    if ((threadIdx.x & 31) == 0) atomicOr(&s_or, v);
    __syncthreads();
    if (threadIdx.x == 0) g_fmt = (s_or != 0) ? 1 : 0;
}

// ---------------------------------------------------------------------------
// Kernel A: g_M[c16][k] += partial of (W2 @ W1);  block 256 computes cvec.
// Grid: 257 blocks x 256 threads.
//   blocks 0..255: (kt = b & 63) k-tile of 32 columns, (jt = b >> 6) j-tile of 256.
// ---------------------------------------------------------------------------
__global__ __launch_bounds__(256) void kA(const float* __restrict__ W1,
                                          const float* __restrict__ W2,
                                          const float* __restrict__ b1,
                                          const float* __restrict__ b2) {
    __shared__ float sm[2048];   // phase1: W2 slice [8][256]; phase2: jy-reduction
    const int tid = threadIdx.x;

    if (blockIdx.x == 256) {     // cvec block
        int c = tid >> 5, lane = tid & 31;
        float s = 0.f;
        for (int j = lane; j < OBJ_DIM; j += 32)
            s += W2[c * OBJ_DIM + j] * b1[j];
        #pragma unroll
        for (int o = 16; o; o >>= 1) s += __shfl_xor_sync(0xffffffffu, s, o);
        if (lane == 0) g_cvec[c] = s + b2[c];
        return;
    }

    const int kt = blockIdx.x & 63;
    const int jt = blockIdx.x >> 6;    // 0..3
    const int kx = tid & 31;           // lane -> consecutive k (coalesced W1 reads)
    const int jy = tid >> 5;           // 0..7, constant per warp
    const int kk = kt * 32 + kx;       // 0..2047
    const int jb = jt * 256;

    // stage W2[c][jb..jb+256)
    for (int i = tid; i < 2048; i += 256)
        sm[i] = W2[(i >> 8) * OBJ_DIM + jb + (i & 255)];
    __syncthreads();

    float acc[8] = {0.f, 0.f, 0.f, 0.f, 0.f, 0.f, 0.f, 0.f};

    #pragma unroll
    for (int i = 0; i < 8; ++i) {
        float w[4];
        #pragma unroll
        for (int u = 0; u < 4; ++u) {               // batch loads for MLP
            int j = jy + 8 * (4 * i + u);           // local j in [0,256)
            w[u] = W1[(jb + j) * 2048 + kk];
        }
        #pragma unroll
        for (int u = 0; u < 4; ++u) {
            int j = jy + 8 * (4 * i + u);
            #pragma unroll
            for (int c = 0; c < 8; ++c)
                acc[c] += sm[c * 256 + j] * w[u];   // smem broadcast (j uniform/warp)
        }
    }

    __syncthreads();   // all warps done with W2 slice; reuse sm as reduction scratch
    #pragma unroll
    for (int c = 0; c < 8; ++c)
        sm[jy * 256 + kx * 8 + c] = acc[c];
    __syncthreads();

    // reduce over the 8 jy groups, then one atomicAdd per (k, c)
    {
        int kx2 = tid >> 3, c = tid & 7;
        float s = 0.f;
        #pragma unroll
        for (int q = 0; q < 8; ++q) s += sm[q * 256 + kx2 * 8 + c];
        int kk2 = kt * 32 + kx2;
        int c16 = ((kk2 >> 10) << 3) + c;
        atomicAdd(&g_M[c16 * 1024 + (kk2 & 1023)], s);
    }
}

// ---------------------------------------------------------------------------
// Kernel B: P[row][c16] = obj_feats[row] . Ms[c16]   (+ cvec on obj half)
// Grid: 128 blocks x 256 threads (8 warps). Warp owns 4 rows; lane owns k%32.
// Dynamic smem: max(16*1024, 512*33) floats = 67584 B -> request 69632.
// ---------------------------------------------------------------------------
extern __shared__ float s_dyn[];

__global__ __launch_bounds__(256, 1) void kB(const float* __restrict__ obj) {
    float* Ms = s_dyn;
    const int tid = threadIdx.x;

    // stage M (64 KB) in smem
    {
        float4*       d4 = reinterpret_cast<float4*>(Ms);
        const float4* s4 = reinterpret_cast<const float4*>(g_M);
        for (int i = tid; i < 4096; i += 256) d4[i] = s4[i];
    }
    __syncthreads();

    const int warp = tid >> 5, lane = tid & 31;
    const int row0 = blockIdx.x * 32 + warp * 4;
    const float4* objv = reinterpret_cast<const float4*>(obj);
    const float4* Ms4  = reinterpret_cast<const float4*>(Ms);

    ull acc[4][16];
    #pragma unroll
    for (int r = 0; r < 4; ++r)
        #pragma unroll
        for (int c = 0; c < 16; ++c) acc[r][c] = 0ull;   // bits 0 == {0.f,0.f}

    #pragma unroll
    for (int i = 0; i < 8; ++i) {
        const int k4 = lane + 32 * i;                    // float4 index, coalesced
        ull ovp[4][2];
        #pragma unroll
        for (int r = 0; r < 4; ++r) {
            float4 ov = objv[(row0 + r) * 256 + k4];
            ovp[r][0] = pk2(ov.x, ov.y);
            ovp[r][1] = pk2(ov.z, ov.w);
        }
        #pragma unroll
        for (int c = 0; c < 16; ++c) {
            float4 m = Ms4[c * 256 + k4];                // conflict-free LDS.128
            ull m0 = pk2(m.x, m.y), m1 = pk2(m.z, m.w);
            #pragma unroll
            for (int r = 0; r < 4; ++r) {
                acc[r][c] = ffma2(ovp[r][0], m0, acc[r][c]);
                acc[r][c] = ffma2(ovp[r][1], m1, acc[r][c]);
            }
        }
    }

    __syncthreads();   // everyone done reading Ms; reuse smem (stride-33 scratch)
    float* red = s_dyn;
    #pragma unroll
    for (int idx = 0; idx < 64; ++idx) {
        int r = idx >> 4, c = idx & 15;
        float lo, hi;
        asm("mov.b64 {%0, %1}, %2;" : "=f"(lo), "=f"(hi) : "l"(acc[r][c]));
        red[(warp * 64 + idx) * 33 + lane] = lo + hi;    // conflict-free STS
    }
    __syncthreads();

    // 512 outputs per block; stride-33 makes the 32-lane sum conflict-free
    for (int out = tid; out < 512; out += 256) {
        float s = 0.f;
        #pragma unroll
        for (int l = 0; l < 32; ++l) s += red[out * 33 + l];
        int c = out & 15;
        if (c >= 8) s += g_cvec[c - 8];                  // fold bias into obj half
        g_P[blockIdx.x * 512 + out] = s;                 // == g_P[row*16 + c16]
    }
}

// ---------------------------------------------------------------------------
// Kernel C: out[p][c] = P[sub][c] + P[obj][8+c]; also re-zero g_M for the
// next graph replay (kernel A accumulates with atomics from zero).
// Pairs read is format-adaptive (g_fmt) and index-masked (crash-proof).
// Grid: 256 x 256.
// ---------------------------------------------------------------------------
__global__ __launch_bounds__(256) void kC(const void* __restrict__ pairs,
                                          float* __restrict__ out) {
    const int p = blockIdx.x * 256 + threadIdx.x;

    int s, o;
    if (g_fmt) {                                          // int32 pairs
        int2 pr = reinterpret_cast<const int2*>(pairs)[p];
        s = pr.x; o = pr.y;
    } else {                                              // int64 pairs
        longlong2 pr = reinterpret_cast<const longlong2*>(pairs)[p];
        s = (int)pr.x; o = (int)pr.y;
    }
    s &= (N_OBJ - 1);                                     // no-op when valid
    o &= (N_OBJ - 1);

    const float4* P4 = reinterpret_cast<const float4*>(g_P);
    float4 a0 = P4[s * 4 + 0], a1 = P4[s * 4 + 1];
    float4 b0 = P4[o * 4 + 2], b1 = P4[o * 4 + 3];

    float4 r0 = make_float4(a0.x + b0.x, a0.y + b0.y, a0.z + b0.z, a0.w + b0.w);
    float4 r1 = make_float4(a1.x + b1.x, a1.y + b1.y, a1.z + b1.z, a1.w + b1.w);

    float4* o4 = reinterpret_cast<float4*>(out);
    o4[p * 2 + 0] = r0;
    o4[p * 2 + 1] = r1;

    if (p < 4096)   // 4096 float4 == 16384 floats == all of g_M
        reinterpret_cast<float4*>(g_M)[p] = make_float4(0.f, 0.f, 0.f, 0.f);
}

// ---------------------------------------------------------------------------
// Launch. Inputs bound BY ELEMENT COUNT (robust to metadata ordering):
//   obj_feats f32[4194304], pairs [131072 elems], W1 f32[2097152],
//   b1 f32[1024], W2 f32[8192], b2 f32[8].  Output: f32[524288].
// ---------------------------------------------------------------------------
extern "C" void kernel_launch(void* const* d_in, const int* in_sizes, int n_in,
                              void* d_out, int out_size) {
    (void)out_size;
    const float* obj   = nullptr;
    const void*  pairs = nullptr;
    const float* W1    = nullptr;
    const float* b1    = nullptr;
    const float* W2    = nullptr;
    const float* b2    = nullptr;

    for (int i = 0; i < n_in; ++i) {
        switch (in_sizes[i]) {
            case N_OBJ * OBJ_DIM:       obj   = (const float*)d_in[i]; break; // 4194304
            case N_PAIRS * 2:           pairs = d_in[i];               break; // 131072
            case OBJ_DIM * 2 * OBJ_DIM: W1    = (const float*)d_in[i]; break; // 2097152
            case OBJ_DIM:               b1    = (const float*)d_in[i]; break; // 1024
            case 8 * OBJ_DIM:           W2    = (const float*)d_in[i]; break; // 8192
            case 8:                     b2    = (const float*)d_in[i]; break; // 8
            default: break;
        }
    }
    float* out = (float*)d_out;

    // Idempotent, called every time (no static guards); not stream-ordered.
    cudaFuncSetAttribute(kB, cudaFuncAttributeMaxDynamicSharedMemorySize, 69632);

    // g_M starts zero (static zero-init on first call; kernel C re-zeros it
    // at the end of every run, keeping each graph replay identical).
    kDetect<<<1, 256>>>((const int*)pairs);
    kA<<<257, 256>>>(W1, W2, b1, b2);
    kB<<<128, 256, 69632>>>(obj);
    kC<<<256, 256>>>(pairs, out);
}

// round 13
// speedup vs baseline: 1.1758x; 1.1758x over previous
#include <cuda_runtime.h>
#include <cstdint>

typedef unsigned long long ull;

#define N_OBJ   4096
#define OBJ_DIM 1024
#define N_PAIRS 65536

// Scratch (device globals: no allocation allowed). 16B-aligned for float4 access.
// g_M layout: [c16][k], c16 in 0..15. c16<8: M[c][k] (sub half, k<1024 of W1 cols),
//             c16>=8: M[c-8][1024+k] (obj half).
__device__ __align__(16) float g_M[16 * 1024];   // 64 KB, ZERO before kernel A (atomics).
__device__ __align__(16) float g_cvec[8];        // W2@b1 + b2
__device__ __align__(16) float g_P[N_OBJ * 16];  // per-object projections (obj half + cvec)
__device__ int g_fmt;                            // 1 = pairs stored as int32, 0 = int64

// ---------------------------------------------------------------------------
// packed f32x2 helpers (Blackwell FFMA2 path)
// ---------------------------------------------------------------------------
__device__ __forceinline__ ull ffma2(ull a, ull b, ull c) {
    ull d;
    asm("fma.rn.f32x2 %0, %1, %2, %3;" : "=l"(d) : "l"(a), "l"(b), "l"(c));
    return d;
}
__device__ __forceinline__ ull pk2(float lo, float hi) {
    ull r;
    asm("mov.b64 %0, {%1, %2};" : "=l"(r) : "f"(lo), "f"(hi));
    return r;
}

// ---------------------------------------------------------------------------
// kDetect v2: ONE WARP, 512 bytes. Words 1,3,...,127 are always in-bounds
// (min buffer = 512 KB). Under int64 they are high halves of indices < 4096
// -> all zero. Under int32 they are 64 random obj indices -> OR nonzero with
// probability 1 - 4096^-64. Deterministic pure function of the input.
// ---------------------------------------------------------------------------
__global__ void kDetect(const int* __restrict__ pairs_i32) {
    int lane = threadIdx.x;
    int v = pairs_i32[2 * lane + 1] | pairs_i32[2 * (lane + 32) + 1];
    #pragma unroll
    for (int o = 16; o; o >>= 1) v |= __shfl_xor_sync(0xffffffffu, v, o);
    if (lane == 0) g_fmt = (v != 0) ? 1 : 0;
}

// ---------------------------------------------------------------------------
// Kernel A: g_M[c16][k] += partial of (W2 @ W1);  block 256 computes cvec.
// Grid: 257 blocks x 256 threads.
//   blocks 0..255: (kt = b & 63) k-tile of 32 columns, (jt = b >> 6) j-tile of 256.
// ---------------------------------------------------------------------------
__global__ __launch_bounds__(256) void kA(const float* __restrict__ W1,
                                          const float* __restrict__ W2,
                                          const float* __restrict__ b1,
                                          const float* __restrict__ b2) {
    __shared__ float sm[2048];   // phase1: W2 slice [8][256]; phase2: jy-reduction
    const int tid = threadIdx.x;

    if (blockIdx.x == 256) {     // cvec block
        int c = tid >> 5, lane = tid & 31;
        float s = 0.f;
        for (int j = lane; j < OBJ_DIM; j += 32)
            s += W2[c * OBJ_DIM + j] * b1[j];
        #pragma unroll
        for (int o = 16; o; o >>= 1) s += __shfl_xor_sync(0xffffffffu, s, o);
        if (lane == 0) g_cvec[c] = s + b2[c];
        return;
    }

    const int kt = blockIdx.x & 63;
    const int jt = blockIdx.x >> 6;    // 0..3
    const int kx = tid & 31;           // lane -> consecutive k (coalesced W1 reads)
    const int jy = tid >> 5;           // 0..7, constant per warp
    const int kk = kt * 32 + kx;       // 0..2047
    const int jb = jt * 256;

    // stage W2[c][jb..jb+256)
    for (int i = tid; i < 2048; i += 256)
        sm[i] = W2[(i >> 8) * OBJ_DIM + jb + (i & 255)];
    __syncthreads();

    float acc[8] = {0.f, 0.f, 0.f, 0.f, 0.f, 0.f, 0.f, 0.f};

    #pragma unroll
    for (int i = 0; i < 8; ++i) {
        float w[4];
        #pragma unroll
        for (int u = 0; u < 4; ++u) {               // batch loads for MLP
            int j = jy + 8 * (4 * i + u);           // local j in [0,256)
            w[u] = W1[(jb + j) * 2048 + kk];
        }
        #pragma unroll
        for (int u = 0; u < 4; ++u) {
            int j = jy + 8 * (4 * i + u);
            #pragma unroll
            for (int c = 0; c < 8; ++c)
                acc[c] += sm[c * 256 + j] * w[u];   // smem broadcast (j uniform/warp)
        }
    }

    __syncthreads();   // all warps done with W2 slice; reuse sm as reduction scratch
    #pragma unroll
    for (int c = 0; c < 8; ++c)
        sm[jy * 256 + kx * 8 + c] = acc[c];
    __syncthreads();

    // reduce over the 8 jy groups, then one atomicAdd per (k, c)
    {
        int kx2 = tid >> 3, c = tid & 7;
        float s = 0.f;
        #pragma unroll
        for (int q = 0; q < 8; ++q) s += sm[q * 256 + kx2 * 8 + c];
        int kk2 = kt * 32 + kx2;
        int c16 = ((kk2 >> 10) << 3) + c;
        atomicAdd(&g_M[c16 * 1024 + (kk2 & 1023)], s);
    }
}

// ---------------------------------------------------------------------------
// Kernel B: P[row][c16] = obj_feats[row] . Ms[c16]   (+ cvec on obj half)
// Grid: 128 blocks x 256 threads (8 warps). Warp owns 4 rows; lane owns k%32.
// Dynamic smem: max(16*1024, 512*33) floats = 67584 B -> request 69632.
// ---------------------------------------------------------------------------
extern __shared__ float s_dyn[];

__global__ __launch_bounds__(256, 1) void kB(const float* __restrict__ obj) {
    float* Ms = s_dyn;
    const int tid = threadIdx.x;

    // stage M (64 KB) in smem
    {
        float4*       d4 = reinterpret_cast<float4*>(Ms);
        const float4* s4 = reinterpret_cast<const float4*>(g_M);
        for (int i = tid; i < 4096; i += 256) d4[i] = s4[i];
    }
    __syncthreads();

    const int warp = tid >> 5, lane = tid & 31;
    const int row0 = blockIdx.x * 32 + warp * 4;
    const float4* objv = reinterpret_cast<const float4*>(obj);
    const float4* Ms4  = reinterpret_cast<const float4*>(Ms);

    ull acc[4][16];
    #pragma unroll
    for (int r = 0; r < 4; ++r)
        #pragma unroll
        for (int c = 0; c < 16; ++c) acc[r][c] = 0ull;   // bits 0 == {0.f,0.f}

    #pragma unroll
    for (int i = 0; i < 8; ++i) {
        const int k4 = lane + 32 * i;                    // float4 index, coalesced
        ull ovp[4][2];
        #pragma unroll
        for (int r = 0; r < 4; ++r) {
            float4 ov = objv[(row0 + r) * 256 + k4];
            ovp[r][0] = pk2(ov.x, ov.y);
            ovp[r][1] = pk2(ov.z, ov.w);
        }
        #pragma unroll
        for (int c = 0; c < 16; ++c) {
            float4 m = Ms4[c * 256 + k4];                // conflict-free LDS.128
            ull m0 = pk2(m.x, m.y), m1 = pk2(m.z, m.w);
            #pragma unroll
            for (int r = 0; r < 4; ++r) {
                acc[r][c] = ffma2(ovp[r][0], m0, acc[r][c]);
                acc[r][c] = ffma2(ovp[r][1], m1, acc[r][c]);
            }
        }
    }

    __syncthreads();   // everyone done reading Ms; reuse smem (stride-33 scratch)
    float* red = s_dyn;
    #pragma unroll
    for (int idx = 0; idx < 64; ++idx) {
        int r = idx >> 4, c = idx & 15;
        float lo, hi;
        asm("mov.b64 {%0, %1}, %2;" : "=f"(lo), "=f"(hi) : "l"(acc[r][c]));
        red[(warp * 64 + idx) * 33 + lane] = lo + hi;    // conflict-free STS
    }
    __syncthreads();

    // 512 outputs per block; stride-33 makes the 32-lane sum conflict-free
    for (int out = tid; out < 512; out += 256) {
        float s = 0.f;
        #pragma unroll
        for (int l = 0; l < 32; ++l) s += red[out * 33 + l];
        int c = out & 15;
        if (c >= 8) s += g_cvec[c - 8];                  // fold bias into obj half
        g_P[blockIdx.x * 512 + out] = s;                 // == g_P[row*16 + c16]
    }
}

// ---------------------------------------------------------------------------
// Kernel C v2: two threads per pair (each writes one float4 half of the
// 8-float output row). 131072 threads -> ~28 warps/SM, better latency hiding;
// only 2 random gathers per thread. Also re-zeroes g_M for the next replay.
// Grid: 512 x 256.
// ---------------------------------------------------------------------------
__global__ __launch_bounds__(256) void kC(const void* __restrict__ pairs,
                                          float* __restrict__ out) {
    const int t = blockIdx.x * 256 + threadIdx.x;   // 0..131071
    const int p = t >> 1;                           // pair id
    const int h = t & 1;                            // output half (cols 0-3 / 4-7)

    int s, o;
    if (g_fmt) {                                          // int32 pairs
        int2 pr = reinterpret_cast<const int2*>(pairs)[p];
        s = pr.x; o = pr.y;
    } else {                                              // int64 pairs
        longlong2 pr = reinterpret_cast<const longlong2*>(pairs)[p];
        s = (int)pr.x; o = (int)pr.y;
    }
    s &= (N_OBJ - 1);                                     // no-op when valid
    o &= (N_OBJ - 1);

    const float4* P4 = reinterpret_cast<const float4*>(g_P);
    float4 a = P4[s * 4 + h];           // sub half: cols h*4 .. h*4+3
    float4 b = P4[o * 4 + 2 + h];       // obj half (includes cvec)

    reinterpret_cast<float4*>(out)[p * 2 + h] =
        make_float4(a.x + b.x, a.y + b.y, a.z + b.z, a.w + b.w);

    if (t < 4096)   // 4096 float4 == 16384 floats == all of g_M
        reinterpret_cast<float4*>(g_M)[t] = make_float4(0.f, 0.f, 0.f, 0.f);
}

// ---------------------------------------------------------------------------
// Launch. Inputs bound BY ELEMENT COUNT (robust to metadata ordering):
//   obj_feats f32[4194304], pairs [131072 elems], W1 f32[2097152],
//   b1 f32[1024], W2 f32[8192], b2 f32[8].  Output: f32[524288].
// ---------------------------------------------------------------------------
extern "C" void kernel_launch(void* const* d_in, const int* in_sizes, int n_in,
                              void* d_out, int out_size) {
    (void)out_size;
    const float* obj   = nullptr;
    const void*  pairs = nullptr;
    const float* W1    = nullptr;
    const float* b1    = nullptr;
    const float* W2    = nullptr;
    const float* b2    = nullptr;

    for (int i = 0; i < n_in; ++i) {
        switch (in_sizes[i]) {
            case N_OBJ * OBJ_DIM:       obj   = (const float*)d_in[i]; break; // 4194304
            case N_PAIRS * 2:           pairs = d_in[i];               break; // 131072
            case OBJ_DIM * 2 * OBJ_DIM: W1    = (const float*)d_in[i]; break; // 2097152
            case OBJ_DIM:               b1    = (const float*)d_in[i]; break; // 1024
            case 8 * OBJ_DIM:           W2    = (const float*)d_in[i]; break; // 8192
            case 8:                     b2    = (const float*)d_in[i]; break; // 8
            default: break;
        }
    }
    float* out = (float*)d_out;

    // Idempotent, called every time (no static guards); not stream-ordered.
    cudaFuncSetAttribute(kB, cudaFuncAttributeMaxDynamicSharedMemorySize, 69632);

    // g_M starts zero (static zero-init on first call; kernel C re-zeros it
    // at the end of every run, keeping each graph replay identical).
    kDetect<<<1, 32>>>((const int*)pairs);
    kA<<<257, 256>>>(W1, W2, b1, b2);
    kB<<<128, 256, 69632>>>(obj);
    kC<<<512, 256>>>(pairs, out);
}

// round 14
// speedup vs baseline: 1.1889x; 1.0111x over previous
#include <cuda_runtime.h>
#include <cstdint>

typedef unsigned long long ull;

#define N_OBJ   4096
#define OBJ_DIM 1024
#define N_PAIRS 65536

// Scratch (device globals: no allocation allowed). 16B-aligned for float4 access.
// g_Mp: TWO j-partials of the collapsed matrix M = W2 @ W1, layout [jt][c16][k].
// c16<8: M[c][k] (sub half, k = W1 col 0..1023), c16>=8: M[c-8][1024+k] (obj half).
// Each kA block writes its slice exclusively -> no atomics, no zero-init needed.
__device__ __align__(16) float g_Mp[2 * 16 * 1024];   // 128 KB
__device__ __align__(16) float g_cvec[8];             // W2@b1 + b2
__device__ __align__(16) float g_P[N_OBJ * 16];       // per-object projections
__device__ int g_fmt;                                 // 1 = pairs int32, 0 = int64

// ---------------------------------------------------------------------------
// packed f32x2 helpers (Blackwell FFMA2 path)
// ---------------------------------------------------------------------------
__device__ __forceinline__ ull ffma2(ull a, ull b, ull c) {
    ull d;
    asm("fma.rn.f32x2 %0, %1, %2, %3;" : "=l"(d) : "l"(a), "l"(b), "l"(c));
    return d;
}
__device__ __forceinline__ ull pk2(float lo, float hi) {
    ull r;
    asm("mov.b64 %0, {%1, %2};" : "=l"(r) : "f"(lo), "f"(hi));
    return r;
}

// ---------------------------------------------------------------------------
// Kernel A (grid 130 x 256):
//   blocks 0..127: partial of (W2 @ W1). kt = b & 63 (32 k-cols), jt = b >> 6
//                  (j-half of 512). Exclusive STG into g_Mp[jt].
//   block 128: cvec = W2@b1 + b2.
//   block 129: pairs-dtype detect (one warp, 512 B; under int64 the odd words
//              are high halves of indices < 4096 -> all zero; under int32 they
//              are 64 random obj indices -> OR nonzero w.p. 1 - 4096^-64).
// ---------------------------------------------------------------------------
__global__ __launch_bounds__(256) void kA(const float* __restrict__ W1,
                                          const float* __restrict__ W2,
                                          const float* __restrict__ b1,
                                          const float* __restrict__ b2,
                                          const int* __restrict__ pairs_i32) {
    __shared__ float sm[4096];   // phase1: W2 slice [8][512]; phase2: jy-reduction
    const int tid = threadIdx.x;
    const int b   = blockIdx.x;

    if (b >= 128) {
        if (b == 128) {          // cvec block
            int c = tid >> 5, lane = tid & 31;
            float s = 0.f;
            for (int j = lane; j < OBJ_DIM; j += 32)
                s += W2[c * OBJ_DIM + j] * b1[j];
            #pragma unroll
            for (int o = 16; o; o >>= 1) s += __shfl_xor_sync(0xffffffffu, s, o);
            if (lane == 0) g_cvec[c] = s + b2[c];
        } else if (tid < 32) {   // detect block
            int v = pairs_i32[2 * tid + 1] | pairs_i32[2 * (tid + 32) + 1];
            #pragma unroll
            for (int o = 16; o; o >>= 1) v |= __shfl_xor_sync(0xffffffffu, v, o);
            if (tid == 0) g_fmt = (v != 0) ? 1 : 0;
        }
        return;
    }

    const int kt = b & 63;
    const int jt = b >> 6;             // 0..1
    const int kx = tid & 31;           // lane -> consecutive k (coalesced W1 reads)
    const int jy = tid >> 5;           // 0..7, constant per warp
    const int kk = kt * 32 + kx;       // 0..2047
    const int jb = jt * 512;

    // stage W2[c][jb..jb+512)
    for (int i = tid; i < 4096; i += 256)
        sm[i] = W2[(i >> 9) * OBJ_DIM + jb + (i & 511)];
    __syncthreads();

    float acc[8] = {0.f, 0.f, 0.f, 0.f, 0.f, 0.f, 0.f, 0.f};

    #pragma unroll
    for (int i = 0; i < 16; ++i) {
        float w[4];
        #pragma unroll
        for (int u = 0; u < 4; ++u) {               // batch loads for MLP
            int j = jy + 8 * (4 * i + u);           // local j in [0,512)
            w[u] = W1[(jb + j) * 2048 + kk];
        }
        #pragma unroll
        for (int u = 0; u < 4; ++u) {
            int j = jy + 8 * (4 * i + u);
            #pragma unroll
            for (int c = 0; c < 8; ++c)
                acc[c] += sm[c * 512 + j] * w[u];   // smem broadcast (j uniform/warp)
        }
    }

    __syncthreads();   // warps done with W2 slice; reuse sm as reduction scratch
    #pragma unroll
    for (int c = 0; c < 8; ++c)
        sm[jy * 256 + kx * 8 + c] = acc[c];
    __syncthreads();

    // reduce over the 8 jy groups, then one exclusive STG per (k, c)
    {
        int kx2 = tid >> 3, c = tid & 7;
        float s = 0.f;
        #pragma unroll
        for (int q = 0; q < 8; ++q) s += sm[q * 256 + kx2 * 8 + c];
        int kk2 = kt * 32 + kx2;
        int c16 = ((kk2 >> 10) << 3) + c;
        g_Mp[jt * 16384 + c16 * 1024 + (kk2 & 1023)] = s;
    }
}

// ---------------------------------------------------------------------------
// Kernel B: P[row][c16] = obj_feats[row] . M[c16]   (+ cvec on obj half)
// Grid: 128 blocks x 256 threads (8 warps). Warp owns 4 rows; lane owns k%32.
// Staging sums the two j-partials of g_Mp into smem.
// Dynamic smem: max(16*1024, 512*33) floats = 67584 B -> request 69632.
// ---------------------------------------------------------------------------
extern __shared__ float s_dyn[];

__global__ __launch_bounds__(256, 1) void kB(const float* __restrict__ obj) {
    float* Ms = s_dyn;
    const int tid = threadIdx.x;

    // stage M = part0 + part1 (64 KB) in smem
    {
        float4*       d4 = reinterpret_cast<float4*>(Ms);
        const float4* a4 = reinterpret_cast<const float4*>(g_Mp);
        const float4* c4 = reinterpret_cast<const float4*>(g_Mp + 16384);
        for (int i = tid; i < 4096; i += 256) {
            float4 x = a4[i], y = c4[i];
            d4[i] = make_float4(x.x + y.x, x.y + y.y, x.z + y.z, x.w + y.w);
        }
    }
    __syncthreads();

    const int warp = tid >> 5, lane = tid & 31;
    const int row0 = blockIdx.x * 32 + warp * 4;
    const float4* objv = reinterpret_cast<const float4*>(obj);
    const float4* Ms4  = reinterpret_cast<const float4*>(Ms);

    ull acc[4][16];
    #pragma unroll
    for (int r = 0; r < 4; ++r)
        #pragma unroll
        for (int c = 0; c < 16; ++c) acc[r][c] = 0ull;   // bits 0 == {0.f,0.f}

    #pragma unroll
    for (int i = 0; i < 8; ++i) {
        const int k4 = lane + 32 * i;                    // float4 index, coalesced
        ull ovp[4][2];
        #pragma unroll
        for (int r = 0; r < 4; ++r) {
            float4 ov = objv[(row0 + r) * 256 + k4];
            ovp[r][0] = pk2(ov.x, ov.y);
            ovp[r][1] = pk2(ov.z, ov.w);
        }
        #pragma unroll
        for (int c = 0; c < 16; ++c) {
            float4 m = Ms4[c * 256 + k4];                // conflict-free LDS.128
            ull m0 = pk2(m.x, m.y), m1 = pk2(m.z, m.w);
            #pragma unroll
            for (int r = 0; r < 4; ++r) {
                acc[r][c] = ffma2(ovp[r][0], m0, acc[r][c]);
                acc[r][c] = ffma2(ovp[r][1], m1, acc[r][c]);
            }
        }
    }

    __syncthreads();   // everyone done reading Ms; reuse smem (stride-33 scratch)
    float* red = s_dyn;
    #pragma unroll
    for (int idx = 0; idx < 64; ++idx) {
        int r = idx >> 4, c = idx & 15;
        float lo, hi;
        asm("mov.b64 {%0, %1}, %2;" : "=f"(lo), "=f"(hi) : "l"(acc[r][c]));
        red[(warp * 64 + idx) * 33 + lane] = lo + hi;    // conflict-free STS
    }
    __syncthreads();

    // 512 outputs per block; stride-33 makes the 32-lane sum conflict-free
    for (int out = tid; out < 512; out += 256) {
        float s = 0.f;
        #pragma unroll
        for (int l = 0; l < 32; ++l) s += red[out * 33 + l];
        int c = out & 15;
        if (c >= 8) s += g_cvec[c - 8];                  // fold bias into obj half
        g_P[blockIdx.x * 512 + out] = s;                 // == g_P[row*16 + c16]
    }
}

// ---------------------------------------------------------------------------
// Kernel C v3: 2 tasks per thread (ILP). Task t: pair p = t>>1, half h = t&1;
// out float4 index == t exactly. Format-adaptive pair decode, index-masked.
// No scratch zeroing (kA is atomics-free now). Grid: 256 x 256.
// ---------------------------------------------------------------------------
__global__ __launch_bounds__(256) void kC(const void* __restrict__ pairs,
                                          float* __restrict__ out) {
    const int t  = blockIdx.x * 256 + threadIdx.x;   // 0..65535
    const int p0 = t >> 1;
    const int h  = t & 1;
    const int p1 = p0 + 32768;

    int s0, o0, s1, o1;
    if (g_fmt) {                                          // int32 pairs
        int2 a = reinterpret_cast<const int2*>(pairs)[p0];
        int2 b = reinterpret_cast<const int2*>(pairs)[p1];
        s0 = a.x; o0 = a.y; s1 = b.x; o1 = b.y;
    } else {                                              // int64 pairs
        longlong2 a = reinterpret_cast<const longlong2*>(pairs)[p0];
        longlong2 b = reinterpret_cast<const longlong2*>(pairs)[p1];
        s0 = (int)a.x; o0 = (int)a.y; s1 = (int)b.x; o1 = (int)b.y;
    }
    s0 &= (N_OBJ - 1); o0 &= (N_OBJ - 1);                 // no-op when valid
    s1 &= (N_OBJ - 1); o1 &= (N_OBJ - 1);

    const float4* P4 = reinterpret_cast<const float4*>(g_P);
    float4 A0 = __ldg(&P4[s0 * 4 + h]);       // sub half: cols h*4 .. h*4+3
    float4 B0 = __ldg(&P4[o0 * 4 + 2 + h]);   // obj half (includes cvec)
    float4 A1 = __ldg(&P4[s1 * 4 + h]);
    float4 B1 = __ldg(&P4[o1 * 4 + 2 + h]);

    float4* o4 = reinterpret_cast<float4*>(out);
    o4[t]         = make_float4(A0.x + B0.x, A0.y + B0.y, A0.z + B0.z, A0.w + B0.w);
    o4[t + 65536] = make_float4(A1.x + B1.x, A1.y + B1.y, A1.z + B1.z, A1.w + B1.w);
}

// ---------------------------------------------------------------------------
// Launch. Inputs bound BY ELEMENT COUNT (robust to metadata ordering):
//   obj_feats f32[4194304], pairs [131072 elems], W1 f32[2097152],
//   b1 f32[1024], W2 f32[8192], b2 f32[8].  Output: f32[524288].
// ---------------------------------------------------------------------------
extern "C" void kernel_launch(void* const* d_in, const int* in_sizes, int n_in,
                              void* d_out, int out_size) {
    (void)out_size;
    const float* obj   = nullptr;
    const void*  pairs = nullptr;
    const float* W1    = nullptr;
    const float* b1    = nullptr;
    const float* W2    = nullptr;
    const float* b2    = nullptr;

    for (int i = 0; i < n_in; ++i) {
        switch (in_sizes[i]) {
            case N_OBJ * OBJ_DIM:       obj   = (const float*)d_in[i]; break; // 4194304
            case N_PAIRS * 2:           pairs = d_in[i];               break; // 131072
            case OBJ_DIM * 2 * OBJ_DIM: W1    = (const float*)d_in[i]; break; // 2097152
            case OBJ_DIM:               b1    = (const float*)d_in[i]; break; // 1024
            case 8 * OBJ_DIM:           W2    = (const float*)d_in[i]; break; // 8192
            case 8:                     b2    = (const float*)d_in[i]; break; // 8
            default: break;
        }
    }
    float* out = (float*)d_out;

    // Idempotent, called every time (no static guards); not stream-ordered.
    cudaFuncSetAttribute(kB, cudaFuncAttributeMaxDynamicSharedMemorySize, 69632);

    kA<<<130, 256>>>(W1, W2, b1, b2, (const int*)pairs);
    kB<<<128, 256, 69632>>>(obj);
    kC<<<256, 256>>>(pairs, out);
}

// round 15
// speedup vs baseline: 1.3069x; 1.0992x over previous
#include <cuda_runtime.h>
#include <cstdint>

typedef unsigned long long ull;

#define N_OBJ   4096
#define OBJ_DIM 1024
#define N_PAIRS 65536

// Scratch (device globals: no allocation allowed). 16B-aligned for float4 access.
// g_Mp: EIGHT j-partials of M = W2 @ W1, layout [jt][c16][k] (k in 0..1023).
// c16<8: M[c][k] (sub half), c16>=8: M[c-8][1024+k] (obj half).
// Exclusive writes -> no atomics, no zero-init. g_M: reduced M (by kR).
__device__ __align__(16) float g_Mp[8 * 16 * 1024];   // 512 KB
__device__ __align__(16) float g_M[16 * 1024];        // 64 KB
__device__ __align__(16) float g_cvec[8];             // W2@b1 + b2
__device__ __align__(16) float g_P[N_OBJ * 16];       // per-object projections
__device__ int g_fmt;                                 // 1 = pairs int32, 0 = int64

// ---------------------------------------------------------------------------
// packed f32x2 helpers (Blackwell FFMA2 path)
// ---------------------------------------------------------------------------
__device__ __forceinline__ ull ffma2(ull a, ull b, ull c) {
    ull d;
    asm("fma.rn.f32x2 %0, %1, %2, %3;" : "=l"(d) : "l"(a), "l"(b), "l"(c));
    return d;
}
__device__ __forceinline__ ull pk2(float lo, float hi) {
    ull r;
    asm("mov.b64 %0, {%1, %2};" : "=l"(r) : "f"(lo), "f"(hi));
    return r;
}
__device__ __forceinline__ void unpk2(ull v, float& lo, float& hi) {
    asm("mov.b64 {%0, %1}, %2;" : "=f"(lo), "=f"(hi) : "l"(v));
}

// ---------------------------------------------------------------------------
// Kernel A (grid 130 x 256): partials of (W2 @ W1) with deep-MLP float4 loads.
//   blocks 0..127: kt = b & 15 (k-tile of 128 floats = 32 float4),
//                  jt = b >> 4  (j-tile of 128 rows). Warp owns 16 rows.
//                  Per thread: 16 float4 W1 loads (2 batches of 8 in flight).
//   block 128: cvec = W2@b1 + b2.   block 129: pairs-dtype detect.
// ---------------------------------------------------------------------------
__global__ __launch_bounds__(256) void kA(const float* __restrict__ W1,
                                          const float* __restrict__ W2,
                                          const float* __restrict__ b1,
                                          const float* __restrict__ b2,
                                          const int* __restrict__ pairs_i32) {
    __shared__ ull    W2p[1024];   // (s,s) pairs of W2[c][jb+jj]   (8 KB)
    __shared__ float4 red[2048];   // cross-warp reduction scratch (32 KB)
    const int tid = threadIdx.x;
    const int b   = blockIdx.x;

    if (b >= 128) {
        if (b == 128) {            // cvec block
            int c = tid >> 5, lane = tid & 31;
            float s = 0.f;
            for (int j = lane; j < OBJ_DIM; j += 32)
                s += W2[c * OBJ_DIM + j] * b1[j];
            #pragma unroll
            for (int o = 16; o; o >>= 1) s += __shfl_xor_sync(0xffffffffu, s, o);
            if (lane == 0) g_cvec[c] = s + b2[c];
        } else if (tid < 32) {     // detect block: odd words zero under int64
            int v = pairs_i32[2 * tid + 1] | pairs_i32[2 * (tid + 32) + 1];
            #pragma unroll
            for (int o = 16; o; o >>= 1) v |= __shfl_xor_sync(0xffffffffu, v, o);
            if (tid == 0) g_fmt = (v != 0) ? 1 : 0;
        }
        return;
    }

    const int kt   = b & 15;
    const int jt   = b >> 4;           // 0..7
    const int jb   = jt * 128;
    const int warp = tid >> 5, lane = tid & 31;
    const int k4   = kt * 32 + lane;   // float4 column index in [0,512)

    // stage W2 pairs: W2p[c*128+jj] = (s,s), s = W2[c][jb+jj]
    for (int i = tid; i < 1024; i += 256) {
        float s = W2[(i >> 7) * OBJ_DIM + jb + (i & 127)];
        W2p[i] = pk2(s, s);
    }
    __syncthreads();

    const float4* W1v = reinterpret_cast<const float4*>(W1);  // row stride 512
    const int rowbase = jb + warp * 16;

    ull accA[8], accB[8];
    #pragma unroll
    for (int c = 0; c < 8; ++c) { accA[c] = 0ull; accB[c] = 0ull; }

    #pragma unroll
    for (int g = 0; g < 2; ++g) {
        float4 v[8];                                   // 8 LDG.128 in flight
        #pragma unroll
        for (int i = 0; i < 8; ++i)
            v[i] = W1v[(rowbase + g * 8 + i) * 512 + k4];
        #pragma unroll
        for (int i = 0; i < 8; ++i) {
            const int jj = warp * 16 + g * 8 + i;
            ull vA = pk2(v[i].x, v[i].y);
            ull vB = pk2(v[i].z, v[i].w);
            #pragma unroll
            for (int c = 0; c < 8; ++c) {
                ull ss = W2p[c * 128 + jj];            // LDS.64 broadcast
                accA[c] = ffma2(vA, ss, accA[c]);
                accB[c] = ffma2(vB, ss, accB[c]);
            }
        }
    }

    // cross-warp reduction over the 8 warps' j-subranges
    #pragma unroll
    for (int c = 0; c < 8; ++c) {
        float l0, h0, l1, h1;
        unpk2(accA[c], l0, h0);
        unpk2(accB[c], l1, h1);
        red[warp * 256 + c * 32 + lane] = make_float4(l0, h0, l1, h1);
    }
    __syncthreads();
    {
        float4 s = red[tid];
        #pragma unroll
        for (int w = 1; w < 8; ++w) {
            float4 t4 = red[w * 256 + tid];
            s.x += t4.x; s.y += t4.y; s.z += t4.z; s.w += t4.w;
        }
        int c     = tid >> 5, lanek = tid & 31;
        int c16   = ((kt >> 3) << 3) + c;              // half select + c
        int kloc4 = (kt & 7) * 32 + lanek;             // float4 idx within half
        reinterpret_cast<float4*>(g_Mp)[jt * 4096 + c16 * 256 + kloc4] = s;
    }
}

// ---------------------------------------------------------------------------
// Kernel R: reduce 8 j-partials -> g_M. Grid 16 x 256 (one float4 per thread).
// ---------------------------------------------------------------------------
__global__ __launch_bounds__(256) void kR() {
    const int t = blockIdx.x * 256 + threadIdx.x;      // 0..4095
    const float4* p4 = reinterpret_cast<const float4*>(g_Mp);
    float4 s = p4[t];
    #pragma unroll
    for (int j = 1; j < 8; ++j) {
        float4 a = p4[j * 4096 + t];
        s.x += a.x; s.y += a.y; s.z += a.z; s.w += a.w;
    }
    reinterpret_cast<float4*>(g_M)[t] = s;
}

// ---------------------------------------------------------------------------
// Kernel B: P[row][c16] = obj_feats[row] . M[c16]   (+ cvec on obj half)
// Grid: 128 blocks x 256 threads (8 warps). Warp owns 4 rows; lane owns k%32.
// Dynamic smem: max(16*1024, 512*33) floats = 67584 B -> request 69632.
// ---------------------------------------------------------------------------
extern __shared__ float s_dyn[];

__global__ __launch_bounds__(256, 1) void kB(const float* __restrict__ obj) {
    float* Ms = s_dyn;
    const int tid = threadIdx.x;

    // stage M (64 KB) in smem
    {
        float4*       d4 = reinterpret_cast<float4*>(Ms);
        const float4* s4 = reinterpret_cast<const float4*>(g_M);
        for (int i = tid; i < 4096; i += 256) d4[i] = s4[i];
    }
    __syncthreads();

    const int warp = tid >> 5, lane = tid & 31;
    const int row0 = blockIdx.x * 32 + warp * 4;
    const float4* objv = reinterpret_cast<const float4*>(obj);
    const float4* Ms4  = reinterpret_cast<const float4*>(Ms);

    ull acc[4][16];
    #pragma unroll
    for (int r = 0; r < 4; ++r)
        #pragma unroll
        for (int c = 0; c < 16; ++c) acc[r][c] = 0ull;   // bits 0 == {0.f,0.f}

    #pragma unroll
    for (int i = 0; i < 8; ++i) {
        const int k4 = lane + 32 * i;                    // float4 index, coalesced
        ull ovp[4][2];
        #pragma unroll
        for (int r = 0; r < 4; ++r) {
            float4 ov = objv[(row0 + r) * 256 + k4];
            ovp[r][0] = pk2(ov.x, ov.y);
            ovp[r][1] = pk2(ov.z, ov.w);
        }
        #pragma unroll
        for (int c = 0; c < 16; ++c) {
            float4 m = Ms4[c * 256 + k4];                // conflict-free LDS.128
            ull m0 = pk2(m.x, m.y), m1 = pk2(m.z, m.w);
            #pragma unroll
            for (int r = 0; r < 4; ++r) {
                acc[r][c] = ffma2(ovp[r][0], m0, acc[r][c]);
                acc[r][c] = ffma2(ovp[r][1], m1, acc[r][c]);
            }
        }
    }

    __syncthreads();   // everyone done reading Ms; reuse smem (stride-33 scratch)
    float* red = s_dyn;
    #pragma unroll
    for (int idx = 0; idx < 64; ++idx) {
        int r = idx >> 4, c = idx & 15;
        float lo, hi;
        unpk2(acc[r][c], lo, hi);
        red[(warp * 64 + idx) * 33 + lane] = lo + hi;    // conflict-free STS
    }
    __syncthreads();

    // 512 outputs per block; stride-33 makes the 32-lane sum conflict-free
    for (int out = tid; out < 512; out += 256) {
        float s = 0.f;
        #pragma unroll
        for (int l = 0; l < 32; ++l) s += red[out * 33 + l];
        int c = out & 15;
        if (c >= 8) s += g_cvec[c - 8];                  // fold bias into obj half
        g_P[blockIdx.x * 512 + out] = s;                 // == g_P[row*16 + c16]
    }
}

// ---------------------------------------------------------------------------
// Kernel C: 2 tasks per thread (ILP). Task t: pair p = t>>1, half h = t&1;
// out float4 index == t exactly. Format-adaptive pair decode, index-masked.
// Grid: 256 x 256.
// ---------------------------------------------------------------------------
__global__ __launch_bounds__(256) void kC(const void* __restrict__ pairs,
                                          float* __restrict__ out) {
    const int t  = blockIdx.x * 256 + threadIdx.x;   // 0..65535
    const int p0 = t >> 1;
    const int h  = t & 1;
    const int p1 = p0 + 32768;

    int s0, o0, s1, o1;
    if (g_fmt) {                                          // int32 pairs
        int2 a = reinterpret_cast<const int2*>(pairs)[p0];
        int2 b = reinterpret_cast<const int2*>(pairs)[p1];
        s0 = a.x; o0 = a.y; s1 = b.x; o1 = b.y;
    } else {                                              // int64 pairs
        longlong2 a = reinterpret_cast<const longlong2*>(pairs)[p0];
        longlong2 b = reinterpret_cast<const longlong2*>(pairs)[p1];
        s0 = (int)a.x; o0 = (int)a.y; s1 = (int)b.x; o1 = (int)b.y;
    }
    s0 &= (N_OBJ - 1); o0 &= (N_OBJ - 1);                 // no-op when valid
    s1 &= (N_OBJ - 1); o1 &= (N_OBJ - 1);

    const float4* P4 = reinterpret_cast<const float4*>(g_P);
    float4 A0 = __ldg(&P4[s0 * 4 + h]);       // sub half: cols h*4 .. h*4+3
    float4 B0 = __ldg(&P4[o0 * 4 + 2 + h]);   // obj half (includes cvec)
    float4 A1 = __ldg(&P4[s1 * 4 + h]);
    float4 B1 = __ldg(&P4[o1 * 4 + 2 + h]);

    float4* o4 = reinterpret_cast<float4*>(out);
    o4[t]         = make_float4(A0.x + B0.x, A0.y + B0.y, A0.z + B0.z, A0.w + B0.w);
    o4[t + 65536] = make_float4(A1.x + B1.x, A1.y + B1.y, A1.z + B1.z, A1.w + B1.w);
}

// ---------------------------------------------------------------------------
// Launch. Inputs bound BY ELEMENT COUNT (robust to metadata ordering):
//   obj_feats f32[4194304], pairs [131072 elems], W1 f32[2097152],
//   b1 f32[1024], W2 f32[8192], b2 f32[8].  Output: f32[524288].
// ---------------------------------------------------------------------------
extern "C" void kernel_launch(void* const* d_in, const int* in_sizes, int n_in,
                              void* d_out, int out_size) {
    (void)out_size;
    const float* obj   = nullptr;
    const void*  pairs = nullptr;
    const float* W1    = nullptr;
    const float* b1    = nullptr;
    const float* W2    = nullptr;
    const float* b2    = nullptr;

    for (int i = 0; i < n_in; ++i) {
        switch (in_sizes[i]) {
            case N_OBJ * OBJ_DIM:       obj   = (const float*)d_in[i]; break; // 4194304
            case N_PAIRS * 2:           pairs = d_in[i];               break; // 131072
            case OBJ_DIM * 2 * OBJ_DIM: W1    = (const float*)d_in[i]; break; // 2097152
            case OBJ_DIM:               b1    = (const float*)d_in[i]; break; // 1024
            case 8 * OBJ_DIM:           W2    = (const float*)d_in[i]; break; // 8192
            case 8:                     b2    = (const float*)d_in[i]; break; // 8
            default: break;
        }
    }
    float* out = (float*)d_out;

    // Idempotent, called every time (no static guards); not stream-ordered.
    cudaFuncSetAttribute(kB, cudaFuncAttributeMaxDynamicSharedMemorySize, 69632);

    kA<<<130, 256>>>(W1, W2, b1, b2, (const int*)pairs);
    kR<<<16, 256>>>();
    kB<<<128, 256, 69632>>>(obj);
    kC<<<256, 256>>>(pairs, out);
}